// round 5
// baseline (speedup 1.0000x reference)
#include <cuda_runtime.h>
#include <stdint.h>

// Problem constants (fixed shapes per reference)
#define N_MAX   100000
#define E_MAX   1600000
#define D       64
#define NB_SCAN ((N_MAX + 255) / 256)   // 391 scan blocks

// ---------------- scratch (static device globals; no allocations) -------------
__device__ int   g_is64;
__device__ int   g_deg[N_MAX];
__device__ float g_dinv[N_MAX];
__device__ int   g_rowptr[N_MAX + 1];
__device__ int   g_cursor[N_MAX];
__device__ int   g_bsum[NB_SCAN + 1];
__device__ int   g_bofs[NB_SCAN + 1];
__device__ int   g_row[E_MAX];
__device__ int   g_col[E_MAX];
__device__ int   g_col_s[E_MAX];
__device__ float g_lap_s[E_MAX];
__device__ float g_tx1[(size_t)N_MAX * D];
__device__ float g_tx2[(size_t)N_MAX * D];

// ---------------- dtype detection ---------------------------------------------
// Interpret the first 256 entries of edge_index as int64. If ANY lies outside
// [0, n), the buffer must be int32 (int32 pairs read as int64 are astronomically
// large with overwhelming probability). If all lie in range, it's int64.
__global__ void k_detect(const void* __restrict__ ei_raw, int n) {
    __shared__ int ok;
    int tid = threadIdx.x;
    if (tid == 0) ok = 1;
    __syncthreads();
    const long long* ei64 = (const long long*)ei_raw;
    long long v = ei64[tid];
    if (v < 0 || v >= (long long)n) ok = 0;
    __syncthreads();
    if (tid == 0) g_is64 = ok;
}

// ---------------- prep kernels -------------------------------------------------
__global__ void k_zero_deg(int n) {
    int i = blockIdx.x * blockDim.x + threadIdx.x;
    if (i < n) g_deg[i] = 0;
}

__global__ void k_prep(const void* __restrict__ ei_raw, int E) {
    int e = blockIdx.x * blockDim.x + threadIdx.x;
    if (e >= E) return;
    int r, c;
    if (g_is64) {
        const long long* ei = (const long long*)ei_raw;
        r = (int)ei[e];
        c = (int)ei[(size_t)E + e];
    } else {
        const int* ei = (const int*)ei_raw;
        r = ei[e];
        c = ei[(size_t)E + e];
    }
    g_row[e] = r;
    g_col[e] = c;
    atomicAdd(&g_deg[r], 1);
}

// block-inclusive scan of g_deg -> g_rowptr[i+1]; per-block totals -> g_bsum
__global__ void k_scan1(int n) {
    __shared__ int s[256];
    int tid = threadIdx.x;
    int i = blockIdx.x * 256 + tid;
    int v = (i < n) ? g_deg[i] : 0;
    s[tid] = v;
    __syncthreads();
#pragma unroll
    for (int ofs = 1; ofs < 256; ofs <<= 1) {
        int t = (tid >= ofs) ? s[tid - ofs] : 0;
        __syncthreads();
        s[tid] += t;
        __syncthreads();
    }
    if (i < n) g_rowptr[i + 1] = s[tid];
    if (tid == 255) g_bsum[blockIdx.x] = s[255];
}

// single-block exclusive scan of block sums (B <= 512)
__global__ void k_scan2(int B) {
    __shared__ int s[512];
    int tid = threadIdx.x;
    int v = (tid < B) ? g_bsum[tid] : 0;
    s[tid] = v;
    __syncthreads();
#pragma unroll
    for (int ofs = 1; ofs < 512; ofs <<= 1) {
        int t = (tid >= ofs) ? s[tid - ofs] : 0;
        __syncthreads();
        s[tid] += t;
        __syncthreads();
    }
    if (tid < B) g_bofs[tid] = s[tid] - v;   // exclusive
}

// finalize rowptr, init scatter cursors, compute dinv
__global__ void k_scan3(int n) {
    int i = blockIdx.x * blockDim.x + threadIdx.x;
    if (i >= n) return;
    int rp = g_rowptr[i + 1] + g_bofs[i >> 8];
    g_rowptr[i + 1] = rp;
    int dg = g_deg[i];
    g_cursor[i] = rp - dg;
    g_dinv[i] = (dg > 0) ? rsqrtf((float)dg) : 0.0f;
    if (i == 0) g_rowptr[0] = 0;
}

__global__ void k_scatter(const float* __restrict__ ea, int E) {
    int e = blockIdx.x * blockDim.x + threadIdx.x;
    if (e >= E) return;
    int r = g_row[e];
    int c = g_col[e];
    int p = atomicAdd(&g_cursor[r], 1);
    g_col_s[p] = c;
    g_lap_s[p] = -g_dinv[r] * ea[e] * g_dinv[c];
}

// ---------------- fused SpMM + recurrence + GEMM epilogue ---------------------
// K = Chebyshev order being produced (1, 2, 3).
//   K==1: t = spmm(x);             store g_tx1; out = bias + x@W0 + t@W1
//   K==2: t = 2*spmm(tx1) - x;     store g_tx2; out += t@W2
//   K==3: t = 2*spmm(tx2) - tx1;                out += t@W3
// One warp per node. h rows gathered as float2/lane (coalesced 256B rows, L2-hit).
template <int K>
__global__ void __launch_bounds__(256) cheb_kernel(
    const float* __restrict__ h,        // T_{k-1}
    const float* __restrict__ prev,     // T_{k-2} (K>=2)
    const float* __restrict__ x,        // original x (K==1 only, for W0 term)
    const float* __restrict__ Wk,       // weight[k], 64x64 row-major (i,j)
    const float* __restrict__ W0g,      // weight[0] (K==1 only)
    const float* __restrict__ bias,     // (K==1 only)
    float* __restrict__ out,
    int n)
{
    __shared__ float sW[D * D];
    __shared__ float sW0[(K == 1) ? (D * D) : 4];
    __shared__ float srow[8 * D];

    int tid = threadIdx.x;
    // stage weights to smem
    for (int i = tid; i < D * D; i += 256) {
        sW[i] = Wk[i];
        if constexpr (K == 1) sW0[i] = W0g[i];
    }
    __syncthreads();

    int warp = tid >> 5;
    int lane = tid & 31;
    int r = blockIdx.x * 8 + warp;
    if (r >= n) return;

    int s  = g_rowptr[r];
    int e2 = g_rowptr[r + 1];

    float2 acc = make_float2(0.0f, 0.0f);
    const unsigned FULL = 0xffffffffu;

    for (int base = s; base < e2; base += 32) {
        int m = e2 - base;
        if (m > 32) m = 32;
        int   cl = 0;
        float ll = 0.0f;
        if (lane < m) {
            cl = g_col_s[base + lane];
            ll = g_lap_s[base + lane];
        }
        int j = 0;
        // 4-wide unroll for MLP on the L2 gathers
        for (; j + 4 <= m; j += 4) {
            int c0 = __shfl_sync(FULL, cl, j + 0);
            int c1 = __shfl_sync(FULL, cl, j + 1);
            int c2 = __shfl_sync(FULL, cl, j + 2);
            int c3 = __shfl_sync(FULL, cl, j + 3);
            float l0 = __shfl_sync(FULL, ll, j + 0);
            float l1 = __shfl_sync(FULL, ll, j + 1);
            float l2 = __shfl_sync(FULL, ll, j + 2);
            float l3 = __shfl_sync(FULL, ll, j + 3);
            float2 h0 = *reinterpret_cast<const float2*>(h + (size_t)c0 * D + lane * 2);
            float2 h1 = *reinterpret_cast<const float2*>(h + (size_t)c1 * D + lane * 2);
            float2 h2 = *reinterpret_cast<const float2*>(h + (size_t)c2 * D + lane * 2);
            float2 h3 = *reinterpret_cast<const float2*>(h + (size_t)c3 * D + lane * 2);
            acc.x = fmaf(l0, h0.x, acc.x); acc.y = fmaf(l0, h0.y, acc.y);
            acc.x = fmaf(l1, h1.x, acc.x); acc.y = fmaf(l1, h1.y, acc.y);
            acc.x = fmaf(l2, h2.x, acc.x); acc.y = fmaf(l2, h2.y, acc.y);
            acc.x = fmaf(l3, h3.x, acc.x); acc.y = fmaf(l3, h3.y, acc.y);
        }
        for (; j < m; ++j) {
            int   cj = __shfl_sync(FULL, cl, j);
            float lj = __shfl_sync(FULL, ll, j);
            float2 hv = *reinterpret_cast<const float2*>(h + (size_t)cj * D + lane * 2);
            acc.x = fmaf(lj, hv.x, acc.x);
            acc.y = fmaf(lj, hv.y, acc.y);
        }
    }

    // Chebyshev recurrence
    float2 t;
    if constexpr (K == 1) {
        t = acc;
    } else {
        float2 pv = *reinterpret_cast<const float2*>(prev + (size_t)r * D + lane * 2);
        t.x = 2.0f * acc.x - pv.x;
        t.y = 2.0f * acc.y - pv.y;
    }
    if constexpr (K == 1)
        *reinterpret_cast<float2*>(g_tx1 + (size_t)r * D + lane * 2) = t;
    if constexpr (K == 2)
        *reinterpret_cast<float2*>(g_tx2 + (size_t)r * D + lane * 2) = t;

    // ---- GEMM epilogue: out[r] (+)= t @ Wk  (and x@W0 for K==1) ----
    float* row = srow + warp * D;
    reinterpret_cast<float2*>(row)[lane] = t;
    __syncwarp();

    float2 o;
    if constexpr (K == 1) {
        o = *reinterpret_cast<const float2*>(bias + lane * 2);
    } else {
        o = *reinterpret_cast<const float2*>(out + (size_t)r * D + lane * 2);
    }

    const float2* Wp = reinterpret_cast<const float2*>(sW);
#pragma unroll 8
    for (int i = 0; i < D; ++i) {
        float  tv = row[i];
        float2 w  = Wp[i * 32 + lane];
        o.x = fmaf(tv, w.x, o.x);
        o.y = fmaf(tv, w.y, o.y);
    }

    if constexpr (K == 1) {
        float2 xv = *reinterpret_cast<const float2*>(x + (size_t)r * D + lane * 2);
        __syncwarp();
        reinterpret_cast<float2*>(row)[lane] = xv;
        __syncwarp();
        const float2* W0p = reinterpret_cast<const float2*>(sW0);
#pragma unroll 8
        for (int i = 0; i < D; ++i) {
            float  tv = row[i];
            float2 w  = W0p[i * 32 + lane];
            o.x = fmaf(tv, w.x, o.x);
            o.y = fmaf(tv, w.y, o.y);
        }
    }

    *reinterpret_cast<float2*>(out + (size_t)r * D + lane * 2) = o;
}

// ---------------- launch -------------------------------------------------------
extern "C" void kernel_launch(void* const* d_in, const int* in_sizes, int n_in,
                              void* d_out, int out_size)
{
    const float* x   = (const float*)d_in[0];
    const void*  ei  = d_in[1];                 // int32 or int64 — detected on device
    const float* ea  = (const float*)d_in[2];
    const float* w   = (const float*)d_in[3];
    const float* b   = (const float*)d_in[4];
    float*       out = (float*)d_out;

    int n = in_sizes[0] / D;       // 100000
    int E = in_sizes[2];           // 1600000

    int nbN = (n + 255) / 256;     // node blocks (also scan block count)
    int nbE = (E + 255) / 256;

    k_detect<<<1, 256>>>(ei, n);
    k_zero_deg<<<nbN, 256>>>(n);
    k_prep<<<nbE, 256>>>(ei, E);
    k_scan1<<<nbN, 256>>>(n);
    k_scan2<<<1, 512>>>(nbN);
    k_scan3<<<nbN, 256>>>(n);
    k_scatter<<<nbE, 256>>>(ea, E);

    float* tx1;  cudaGetSymbolAddress((void**)&tx1, g_tx1);
    float* tx2;  cudaGetSymbolAddress((void**)&tx2, g_tx2);

    int gb = (n + 7) / 8;  // one warp per node, 8 warps/block
    cheb_kernel<1><<<gb, 256>>>(x,   nullptr, x, w + 1 * D * D, w, b, out, n);
    cheb_kernel<2><<<gb, 256>>>(tx1, x,   nullptr, w + 2 * D * D, nullptr, nullptr, out, n);
    cheb_kernel<3><<<gb, 256>>>(tx2, tx1, nullptr, w + 3 * D * D, nullptr, nullptr, out, n);
}